// round 1
// baseline (speedup 1.0000x reference)
#include <cuda_runtime.h>
#include <math.h>

#define S   256
#define Hd  512
#define E   64
#define R   32
#define L   9
#define BMAX 1024

// Scratch (device globals; no allocation allowed)
__device__ float g_H[4 * BMAX * Hd];   // tanh(x@W1+b1) for modules {e0, r0, r1, r2}
__device__ float g_e0[BMAX * E];
__device__ float g_r[3 * BMAX * R];

// ---------------------------------------------------------------------------
// Kernel 1: H = tanh(x @ W1 + b1) ; GEMM M=B, N=4*512, K=256, 64x64 tiles
// ---------------------------------------------------------------------------
__global__ __launch_bounds__(256) void k1_gemm_tanh(
    const float* __restrict__ x,
    const float* __restrict__ eW1, const float* __restrict__ eb1,
    const float* __restrict__ rW1, const float* __restrict__ rb1,
    int B)
{
    const int bn = blockIdx.x;            // 0..31 : n-block of 64 (2048 cols total)
    const int bm = blockIdx.y;            // row block of 64
    const int m  = bn >> 3;               // module 0..3
    const int cb = (bn & 7) * 64;         // col base within module
    const float* W    = (m == 0) ? eW1 : (rW1 + (size_t)(m - 1) * S * Hd);
    const float* bias = (m == 0) ? eb1 : (rb1 + (size_t)(m - 1) * Hd);

    __shared__ float As[16][68];
    __shared__ float Ws[16][68];

    const int tid = threadIdx.x;
    const int tx = tid & 15;              // n quad
    const int ty = tid >> 4;              // m quad
    float acc[4][4] = {};

    const int rowBase = bm * 64;
    const int la_row = tid >> 2;          // 0..63
    const int la_q   = tid & 3;           // float4 index within 16-k chunk
    const int lw_k   = tid >> 4;          // 0..15
    const int lw_q   = tid & 15;          // 0..15

    for (int k0 = 0; k0 < S; k0 += 16) {
        float4 av = *(const float4*)&x[(size_t)(rowBase + la_row) * S + k0 + la_q * 4];
        float4 wv = *(const float4*)&W[(size_t)(k0 + lw_k) * Hd + cb + lw_q * 4];
        __syncthreads();
        As[la_q * 4 + 0][la_row] = av.x;
        As[la_q * 4 + 1][la_row] = av.y;
        As[la_q * 4 + 2][la_row] = av.z;
        As[la_q * 4 + 3][la_row] = av.w;
        *(float4*)&Ws[lw_k][lw_q * 4] = wv;
        __syncthreads();
        #pragma unroll
        for (int kk = 0; kk < 16; kk++) {
            float4 a = *(const float4*)&As[kk][ty * 4];
            float4 w = *(const float4*)&Ws[kk][tx * 4];
            float av4[4] = {a.x, a.y, a.z, a.w};
            float wv4[4] = {w.x, w.y, w.z, w.w};
            #pragma unroll
            for (int i = 0; i < 4; i++)
                #pragma unroll
                for (int j = 0; j < 4; j++)
                    acc[i][j] += av4[i] * wv4[j];
        }
    }

    float bv[4];
    #pragma unroll
    for (int j = 0; j < 4; j++) bv[j] = bias[cb + tx * 4 + j];

    #pragma unroll
    for (int i = 0; i < 4; i++) {
        int row = rowBase + ty * 4 + i;
        #pragma unroll
        for (int j = 0; j < 4; j++) {
            int col = cb + tx * 4 + j;
            g_H[((size_t)m * B + row) * Hd + col] = tanhf(acc[i][j] + bv[j]);
        }
    }
}

// ---------------------------------------------------------------------------
// Kernel 2: e0 = H_e @ eW2 + eb2 (O=64) ; r_k = H_rk @ rW2_k + rb2_k (O=32)
// One thread per 4 consecutive outputs, K=512 serial.
// ---------------------------------------------------------------------------
__global__ __launch_bounds__(256) void k2_layer2(
    const float* __restrict__ eW2, const float* __restrict__ eb2,
    const float* __restrict__ rW2, const float* __restrict__ rb2,
    int B)
{
    int qid = blockIdx.x * 256 + threadIdx.x;
    if (qid >= B * 40) return;                 // 16 quads (e) + 3*8 quads (r) per batch
    int b = qid / 40;
    int t = qid % 40;

    int m, o4, O;
    const float* W2; const float* b2; float* outp;
    if (t < 16) {
        m = 0; o4 = t; O = 64;
        W2 = eW2; b2 = eb2;
        outp = g_e0 + (size_t)b * E;
    } else {
        int k = (t - 16) / 8; o4 = (t - 16) % 8;
        m = 1 + k; O = 32;
        W2 = rW2 + (size_t)k * Hd * R; b2 = rb2 + k * R;
        outp = g_r + ((size_t)k * B + b) * R;
    }
    const float* h = g_H + ((size_t)m * B + b) * Hd;

    float4 acc = make_float4(b2[o4*4+0], b2[o4*4+1], b2[o4*4+2], b2[o4*4+3]);
    #pragma unroll 4
    for (int hh = 0; hh < Hd; hh++) {
        float hv = __ldg(&h[hh]);
        float4 w = *(const float4*)&W2[(size_t)hh * O + o4 * 4];
        acc.x += hv * w.x; acc.y += hv * w.y;
        acc.z += hv * w.z; acc.w += hv * w.w;
    }
    *(float4*)&outp[o4 * 4] = acc;
}

// ---------------------------------------------------------------------------
// Kernel 3: one CTA per batch. Single pass over tpr[b] builds
//   A_k[e,f] = sum_r r_k[r] * tpr[b,e,r,f]   (k=0,1,2)  in smem (48KB),
// then the sequential i1/i2/i3 chain with layernorm, then @Z.
// ---------------------------------------------------------------------------
__global__ __launch_bounds__(256) void k3_main(
    const float* __restrict__ tpr,
    const float* __restrict__ ln_g, const float* __restrict__ ln_b,
    const float* __restrict__ Z,
    float* __restrict__ out, int B)
{
    extern __shared__ float sm[];
    float* sA   = sm;                 // 3*64*64 = 12288 floats
    float* scur = sA + 3 * E * E;     // 64
    float* ssum = scur + E;           // 64
    float* srv  = ssum + E;           // 96
    float* sred = srv + 96;           // 4

    const int b   = blockIdx.x;
    const int tid = threadIdx.x;

    if (tid < 96) srv[tid] = g_r[(((size_t)(tid >> 5)) * B + b) * R + (tid & 31)];
    if (tid < E)  { scur[tid] = g_e0[(size_t)b * E + tid]; ssum[tid] = 0.0f; }
    __syncthreads();

    // --- A pass: read tpr[b] once (512 KB), 3 FMAs per element ---
    const int f4 = tid & 15;          // float4 along f
    const int eg = tid >> 4;          // 0..15
    #pragma unroll
    for (int j = 0; j < 4; j++) {
        int e = eg + j * 16;
        const float4* p = (const float4*)tpr + (((size_t)b * E + e) * R) * 16 + f4;
        float4 a0 = make_float4(0,0,0,0), a1 = a0, a2 = a0;
        #pragma unroll
        for (int r = 0; r < R; r++) {
            float4 t  = p[(size_t)r * 16];
            float r0 = srv[r], r1 = srv[32 + r], r2 = srv[64 + r];
            a0.x += r0 * t.x; a0.y += r0 * t.y; a0.z += r0 * t.z; a0.w += r0 * t.w;
            a1.x += r1 * t.x; a1.y += r1 * t.y; a1.z += r1 * t.z; a1.w += r1 * t.w;
            a2.x += r2 * t.x; a2.y += r2 * t.y; a2.z += r2 * t.z; a2.w += r2 * t.w;
        }
        *(float4*)&sA[(0 * E + e) * E + f4 * 4] = a0;
        *(float4*)&sA[(1 * E + e) * E + f4 * 4] = a1;
        *(float4*)&sA[(2 * E + e) * E + f4 * 4] = a2;
    }
    __syncthreads();

    // --- chain: i_{k+1} = LN( cur @ A_k ) ; ssum += i ---
    for (int step = 0; step < 3; step++) {
        float sval = 0.0f;
        if (tid < E) {
            const float* Ak = &sA[step * E * E];
            #pragma unroll 16
            for (int e = 0; e < E; e++) sval += scur[e] * Ak[e * E + tid];
            float s1 = sval, s2 = sval * sval;
            #pragma unroll
            for (int o = 16; o; o >>= 1) {
                s1 += __shfl_xor_sync(0xffffffffu, s1, o);
                s2 += __shfl_xor_sync(0xffffffffu, s2, o);
            }
            if ((tid & 31) == 0) { sred[(tid >> 5) * 2] = s1; sred[(tid >> 5) * 2 + 1] = s2; }
        }
        __syncthreads();
        if (tid < E) {
            float s1 = sred[0] + sred[2];
            float s2 = sred[1] + sred[3];
            float mu  = s1 * (1.0f / 64.0f);
            float var = s2 * (1.0f / 64.0f) - mu * mu;
            float inv = rsqrtf(var + 1e-6f);
            float iv  = ln_g[step * E + tid] * (sval - mu) * inv + ln_b[step * E + tid];
            scur[tid] = iv;
            ssum[tid] += iv;
        }
        __syncthreads();
    }

    // --- out[b,:] = step_sum @ Z ---
    if (tid < L) {
        float acc = 0.0f;
        #pragma unroll 8
        for (int f = 0; f < E; f++) acc += ssum[f] * Z[f * L + tid];
        out[(size_t)b * L + tid] = acc;
    }
}

// ---------------------------------------------------------------------------
extern "C" void kernel_launch(void* const* d_in, const int* in_sizes, int n_in,
                              void* d_out, int out_size)
{
    const float* x    = (const float*)d_in[0];
    const float* tpr  = (const float*)d_in[1];
    const float* eW1  = (const float*)d_in[2];
    const float* eb1  = (const float*)d_in[3];
    const float* eW2  = (const float*)d_in[4];
    const float* eb2  = (const float*)d_in[5];
    const float* rW1  = (const float*)d_in[6];
    const float* rb1  = (const float*)d_in[7];
    const float* rW2  = (const float*)d_in[8];
    const float* rb2  = (const float*)d_in[9];
    const float* ln_g = (const float*)d_in[10];
    const float* ln_b = (const float*)d_in[11];
    const float* Z    = (const float*)d_in[12];
    float* out = (float*)d_out;

    int B = in_sizes[0] / S;   // 1024

    dim3 g1(32, B / 64);
    k1_gemm_tanh<<<g1, 256>>>(x, eW1, eb1, rW1, rb1, B);

    int total = B * 40;
    k2_layer2<<<(total + 255) / 256, 256>>>(eW2, eb2, rW2, rb2, B);

    size_t smem = (size_t)(3 * E * E + E + E + 96 + 8) * sizeof(float);
    cudaFuncSetAttribute(k3_main, cudaFuncAttributeMaxDynamicSharedMemorySize, (int)smem);
    k3_main<<<B, 256, smem>>>(tpr, ln_g, ln_b, Z, out, B);
}

// round 2
// speedup vs baseline: 1.1894x; 1.1894x over previous
#include <cuda_runtime.h>
#include <math.h>

#define S   256
#define Hd  512
#define E   64
#define R   32
#define L   9
#define BMAX 1024

// Scratch (device globals; no allocation allowed)
__device__ float g_H[4 * BMAX * Hd];   // tanh(x@W1+b1) for modules {e0, r0, r1, r2}
__device__ float g_e0[BMAX * E];
__device__ float g_r[3 * BMAX * R];

// ---------------------------------------------------------------------------
// Packed f32x2 helpers (Blackwell FFMA2 — ptxas never emits this from C++)
// ---------------------------------------------------------------------------
__device__ __forceinline__ unsigned long long pk2(float x, float y) {
    unsigned long long r;
    asm("mov.b64 %0, {%1, %2};" : "=l"(r) : "f"(x), "f"(y));
    return r;
}
__device__ __forceinline__ void fma2(unsigned long long& d,
                                     unsigned long long a, unsigned long long b) {
    asm("fma.rn.f32x2 %0, %1, %2, %0;" : "+l"(d) : "l"(a), "l"(b));
}
__device__ __forceinline__ float2 upk(unsigned long long v) {
    float2 f;
    asm("mov.b64 {%0, %1}, %2;" : "=f"(f.x), "=f"(f.y) : "l"(v));
    return f;
}

// ---------------------------------------------------------------------------
// Kernel 1: H = tanh(x @ W1 + b1) ; GEMM M=B, N=4*512, K=256
// 128x64 tiles, 256 threads, 8x4 micro-tile via f32x2 (m-paired accumulators)
// ---------------------------------------------------------------------------
__global__ __launch_bounds__(256) void k1_gemm_tanh(
    const float* __restrict__ x,
    const float* __restrict__ eW1, const float* __restrict__ eb1,
    const float* __restrict__ rW1, const float* __restrict__ rb1,
    int B)
{
    const int bn = blockIdx.x;            // 0..31 : module m=bn>>3, colbase=(bn&7)*64
    const int bm = blockIdx.y;            // row block of 128
    const int m  = bn >> 3;
    const int cb = (bn & 7) * 64;
    const float* W    = (m == 0) ? eW1 : (rW1 + (size_t)(m - 1) * S * Hd);
    const float* bias = (m == 0) ? eb1 : (rb1 + (size_t)(m - 1) * Hd);

    __shared__ float As[16][132];   // [k][m] transposed
    __shared__ float Bs[16][68];    // [k][n]

    const int tid = threadIdx.x;
    const int tx  = tid & 15;             // n: 4 cols each
    const int ty  = tid >> 4;             // m: 8 rows each (as 4 pairs)
    const int rowBase = bm * 128;

    const int a_row = tid >> 1;           // 0..127
    const int a_q   = (tid & 1) * 2;      // float4 index: q, q+1
    const int b_k   = tid >> 4;
    const int b_n4  = tid & 15;

    unsigned long long acc[4][4];         // [m-pair][n]
    #pragma unroll
    for (int i = 0; i < 4; i++)
        #pragma unroll
        for (int j = 0; j < 4; j++) acc[i][j] = 0ull;

    for (int k0 = 0; k0 < S; k0 += 16) {
        const float* xrow = &x[(size_t)(rowBase + a_row) * S + k0];
        float4 av0 = *(const float4*)&xrow[a_q * 4];
        float4 av1 = *(const float4*)&xrow[a_q * 4 + 4];
        float4 wv  = *(const float4*)&W[(size_t)(k0 + b_k) * Hd + cb + b_n4 * 4];
        __syncthreads();
        As[a_q * 4 + 0][a_row] = av0.x;
        As[a_q * 4 + 1][a_row] = av0.y;
        As[a_q * 4 + 2][a_row] = av0.z;
        As[a_q * 4 + 3][a_row] = av0.w;
        As[a_q * 4 + 4][a_row] = av1.x;
        As[a_q * 4 + 5][a_row] = av1.y;
        As[a_q * 4 + 6][a_row] = av1.z;
        As[a_q * 4 + 7][a_row] = av1.w;
        *(float4*)&Bs[b_k][b_n4 * 4] = wv;
        __syncthreads();
        #pragma unroll
        for (int kk = 0; kk < 16; kk++) {
            float4 A0 = *(const float4*)&As[kk][ty * 8];
            float4 A1 = *(const float4*)&As[kk][ty * 8 + 4];
            float4 Wv = *(const float4*)&Bs[kk][tx * 4];
            unsigned long long am[4] = { pk2(A0.x, A0.y), pk2(A0.z, A0.w),
                                         pk2(A1.x, A1.y), pk2(A1.z, A1.w) };
            unsigned long long wd[4] = { pk2(Wv.x, Wv.x), pk2(Wv.y, Wv.y),
                                         pk2(Wv.z, Wv.z), pk2(Wv.w, Wv.w) };
            #pragma unroll
            for (int i = 0; i < 4; i++)
                #pragma unroll
                for (int j = 0; j < 4; j++)
                    fma2(acc[i][j], am[i], wd[j]);
        }
    }

    float bv[4];
    #pragma unroll
    for (int j = 0; j < 4; j++) bv[j] = bias[cb + tx * 4 + j];

    #pragma unroll
    for (int i = 0; i < 4; i++) {
        int r0 = rowBase + ty * 8 + 2 * i;
        #pragma unroll
        for (int j = 0; j < 4; j++) {
            float2 v = upk(acc[i][j]);
            int col = cb + tx * 4 + j;
            g_H[((size_t)m * B + r0)     * Hd + col] = tanhf(v.x + bv[j]);
            g_H[((size_t)m * B + r0 + 1) * Hd + col] = tanhf(v.y + bv[j]);
        }
    }
}

// ---------------------------------------------------------------------------
// Kernel 2: tiled GEMM layer2. M-tile 32 rows, N = full module width (64 or 32)
// ---------------------------------------------------------------------------
template<int O>
__device__ __forceinline__ void k2_body(
    const float* __restrict__ Hb, const float* __restrict__ W2,
    const float* __restrict__ bias, float* __restrict__ outp,
    int B, float* sm)
{
    constexpr int TX = O / 4;             // threads along n (16 or 8)
    constexpr int RT = 32 * TX / 256;     // rows per thread (2 or 1)
    float* Hs = sm;                       // [32 k][36 m]
    float* Ws = sm + 32 * 36;             // [32 k][O+4]

    const int tid = threadIdx.x;
    const int rowBase = blockIdx.x * 32;
    const int tx = tid % TX;
    const int ty = tid / TX;

    // H tile load indices: 32 rows x 32 k = 256 float4, 1/thread
    const int h_row = tid >> 3;
    const int h_q   = tid & 7;

    float acc[RT][4];
    #pragma unroll
    for (int i = 0; i < RT; i++)
        #pragma unroll
        for (int j = 0; j < 4; j++) acc[i][j] = 0.0f;

    for (int k0 = 0; k0 < Hd; k0 += 32) {
        float4 hv = *(const float4*)&Hb[(size_t)(rowBase + h_row) * Hd + k0 + h_q * 4];
        float4 wv[2];
        #pragma unroll
        for (int it = 0; it < (8 * O) / 256; it++) {
            int i = tid + it * 256;
            int k  = i / TX;
            int n4 = i % TX;
            wv[it] = *(const float4*)&W2[(size_t)(k0 + k) * O + n4 * 4];
        }
        __syncthreads();
        Hs[(h_q * 4 + 0) * 36 + h_row] = hv.x;
        Hs[(h_q * 4 + 1) * 36 + h_row] = hv.y;
        Hs[(h_q * 4 + 2) * 36 + h_row] = hv.z;
        Hs[(h_q * 4 + 3) * 36 + h_row] = hv.w;
        #pragma unroll
        for (int it = 0; it < (8 * O) / 256; it++) {
            int i = tid + it * 256;
            int k  = i / TX;
            int n4 = i % TX;
            *(float4*)&Ws[k * (O + 4) + n4 * 4] = wv[it];
        }
        __syncthreads();
        #pragma unroll
        for (int kk = 0; kk < 32; kk++) {
            float a[RT];
            #pragma unroll
            for (int i = 0; i < RT; i++) a[i] = Hs[kk * 36 + ty * RT + i];
            float4 w = *(const float4*)&Ws[kk * (O + 4) + tx * 4];
            #pragma unroll
            for (int i = 0; i < RT; i++) {
                acc[i][0] += a[i] * w.x;
                acc[i][1] += a[i] * w.y;
                acc[i][2] += a[i] * w.z;
                acc[i][3] += a[i] * w.w;
            }
        }
    }

    float bv[4];
    #pragma unroll
    for (int j = 0; j < 4; j++) bv[j] = bias[tx * 4 + j];
    #pragma unroll
    for (int i = 0; i < RT; i++) {
        int row = rowBase + ty * RT + i;
        #pragma unroll
        for (int j = 0; j < 4; j++)
            outp[(size_t)row * O + tx * 4 + j] = acc[i][j] + bv[j];
    }
}

__global__ __launch_bounds__(256) void k2_all(
    const float* __restrict__ eW2, const float* __restrict__ eb2,
    const float* __restrict__ rW2, const float* __restrict__ rb2, int B)
{
    extern __shared__ float sm2[];
    if (blockIdx.y == 0) {
        k2_body<64>(g_H, eW2, eb2, g_e0, B, sm2);
    } else {
        int km = blockIdx.y - 1;
        k2_body<32>(g_H + (size_t)(1 + km) * B * Hd,
                    rW2 + (size_t)km * Hd * R, rb2 + km * R,
                    g_r + (size_t)km * B * R, B, sm2);
    }
}

// ---------------------------------------------------------------------------
// Kernel 3: one CTA per batch. Single pass over tpr[b] builds
//   A_k[e,f] = sum_r r_k[r] * tpr[b,e,r,f]   (k=0,1,2) in smem via f32x2,
// then the sequential i1/i2/i3 chain with layernorm, then @Z.
// ---------------------------------------------------------------------------
__global__ __launch_bounds__(256) void k3_main(
    const float* __restrict__ tpr,
    const float* __restrict__ ln_g, const float* __restrict__ ln_b,
    const float* __restrict__ Z,
    float* __restrict__ out, int B)
{
    extern __shared__ float sm[];
    float*  sA   = sm;                        // 3*64*64 = 12288 floats
    float*  scur = sA + 3 * E * E;            // 64
    float*  ssum = scur + E;                  // 64
    float2* srv2 = (float2*)(ssum + E);       // 96 float2 (duplicated coefs)
    float*  sred = (float*)(srv2 + 96);       // 4

    const int b   = blockIdx.x;
    const int tid = threadIdx.x;

    if (tid < 96) {
        float v = g_r[((size_t)(tid >> 5) * B + b) * R + (tid & 31)];
        srv2[tid] = make_float2(v, v);
    }
    if (tid < E) { scur[tid] = g_e0[(size_t)b * E + tid]; ssum[tid] = 0.0f; }
    __syncthreads();

    // --- A pass: read tpr[b] once (512 KB), 6 FFMA2 per 16B load ---
    const int f4 = tid & 15;
    const int eg = tid >> 4;
    #pragma unroll
    for (int j = 0; j < 4; j++) {
        const int e = eg + j * 16;
        const float4* p = (const float4*)tpr + ((size_t)b * E + e) * (R * 16) + f4;
        unsigned long long a00 = 0, a01 = 0, a10 = 0, a11 = 0, a20 = 0, a21 = 0;
        #pragma unroll
        for (int r = 0; r < R; r++) {
            float4 t = __ldcs(&p[(size_t)r * 16]);
            unsigned long long t01 = pk2(t.x, t.y);
            unsigned long long t23 = pk2(t.z, t.w);
            float2 c0f = srv2[r], c1f = srv2[32 + r], c2f = srv2[64 + r];
            unsigned long long c0 = *(unsigned long long*)&c0f;
            unsigned long long c1 = *(unsigned long long*)&c1f;
            unsigned long long c2 = *(unsigned long long*)&c2f;
            fma2(a00, c0, t01); fma2(a01, c0, t23);
            fma2(a10, c1, t01); fma2(a11, c1, t23);
            fma2(a20, c2, t01); fma2(a21, c2, t23);
        }
        *(float2*)&sA[(0 * E + e) * E + f4 * 4]     = upk(a00);
        *(float2*)&sA[(0 * E + e) * E + f4 * 4 + 2] = upk(a01);
        *(float2*)&sA[(1 * E + e) * E + f4 * 4]     = upk(a10);
        *(float2*)&sA[(1 * E + e) * E + f4 * 4 + 2] = upk(a11);
        *(float2*)&sA[(2 * E + e) * E + f4 * 4]     = upk(a20);
        *(float2*)&sA[(2 * E + e) * E + f4 * 4 + 2] = upk(a21);
    }
    __syncthreads();

    // --- chain: i_{k+1} = LN( cur @ A_k ) ; ssum += i ---
    for (int step = 0; step < 3; step++) {
        float sval = 0.0f;
        if (tid < E) {
            const float* Ak = &sA[step * E * E];
            #pragma unroll 16
            for (int e = 0; e < E; e++) sval += scur[e] * Ak[e * E + tid];
            float s1 = sval, s2 = sval * sval;
            #pragma unroll
            for (int o = 16; o; o >>= 1) {
                s1 += __shfl_xor_sync(0xffffffffu, s1, o);
                s2 += __shfl_xor_sync(0xffffffffu, s2, o);
            }
            if ((tid & 31) == 0) { sred[(tid >> 5) * 2] = s1; sred[(tid >> 5) * 2 + 1] = s2; }
        }
        __syncthreads();
        if (tid < E) {
            float s1 = sred[0] + sred[2];
            float s2 = sred[1] + sred[3];
            float mu  = s1 * (1.0f / 64.0f);
            float var = s2 * (1.0f / 64.0f) - mu * mu;
            float inv = rsqrtf(var + 1e-6f);
            float iv  = ln_g[step * E + tid] * (sval - mu) * inv + ln_b[step * E + tid];
            scur[tid] = iv;
            ssum[tid] += iv;
        }
        __syncthreads();
    }

    // --- out[b,:] = step_sum @ Z ---
    if (tid < L) {
        float acc = 0.0f;
        #pragma unroll 8
        for (int f = 0; f < E; f++) acc += ssum[f] * Z[f * L + tid];
        out[(size_t)b * L + tid] = acc;
    }
}

// ---------------------------------------------------------------------------
extern "C" void kernel_launch(void* const* d_in, const int* in_sizes, int n_in,
                              void* d_out, int out_size)
{
    const float* x    = (const float*)d_in[0];
    const float* tpr  = (const float*)d_in[1];
    const float* eW1  = (const float*)d_in[2];
    const float* eb1  = (const float*)d_in[3];
    const float* eW2  = (const float*)d_in[4];
    const float* eb2  = (const float*)d_in[5];
    const float* rW1  = (const float*)d_in[6];
    const float* rb1  = (const float*)d_in[7];
    const float* rW2  = (const float*)d_in[8];
    const float* rb2  = (const float*)d_in[9];
    const float* ln_g = (const float*)d_in[10];
    const float* ln_b = (const float*)d_in[11];
    const float* Z    = (const float*)d_in[12];
    float* out = (float*)d_out;

    int B = in_sizes[0] / S;   // 1024

    dim3 g1(32, B / 128);
    k1_gemm_tanh<<<g1, 256>>>(x, eW1, eb1, rW1, rb1, B);

    dim3 g2(B / 32, 4);
    size_t smem2 = (size_t)(32 * 36 + 32 * 68) * sizeof(float);
    k2_all<<<g2, 256, smem2>>>(eW2, eb2, rW2, rb2, B);

    size_t smem3 = (size_t)(3 * E * E + E + E) * sizeof(float)
                 + 96 * sizeof(float2) + 8 * sizeof(float);
    cudaFuncSetAttribute(k3_main, cudaFuncAttributeMaxDynamicSharedMemorySize, (int)smem3);
    k3_main<<<B, 256, smem3>>>(tpr, ln_g, ln_b, Z, out, B);
}

// round 3
// speedup vs baseline: 1.5662x; 1.3168x over previous
#include <cuda_runtime.h>
#include <math.h>

#define S   256
#define Hd  512
#define E   64
#define R   32
#define L   9
#define BMAX 1024

typedef unsigned long long u64;

// Scratch (device globals; no allocation allowed)
__device__ float g_H[4 * BMAX * Hd];   // tanh(x@W1+b1) for modules {e0, r0, r1, r2}
__device__ float g_e0[BMAX * E];
__device__ float g_r[3 * BMAX * R];

// ---------------------------------------------------------------------------
// Packed f32x2 helpers (Blackwell FFMA2 — ptxas never emits this from C++)
// ---------------------------------------------------------------------------
__device__ __forceinline__ u64 pk2(float x, float y) {
    u64 r;
    asm("mov.b64 %0, {%1, %2};" : "=l"(r) : "f"(x), "f"(y));
    return r;
}
__device__ __forceinline__ void fma2(u64& d, u64 a, u64 b) {
    asm("fma.rn.f32x2 %0, %1, %2, %0;" : "+l"(d) : "l"(a), "l"(b));
}
__device__ __forceinline__ float2 upk(u64 v) {
    float2 f;
    asm("mov.b64 {%0, %1}, %2;" : "=f"(f.x), "=f"(f.y) : "l"(v));
    return f;
}

// ---------------------------------------------------------------------------
// Kernel 1: H = tanh(x @ W1 + b1) ; GEMM M=B, N=4*512, K=256
// Round-1 64x64 tiling (proven layout/occupancy), inner product via FFMA2:
// acc pairs along n, A duplicated per-lane via mov, W pairs free from float4.
// ---------------------------------------------------------------------------
__global__ __launch_bounds__(256) void k1_gemm_tanh(
    const float* __restrict__ x,
    const float* __restrict__ eW1, const float* __restrict__ eb1,
    const float* __restrict__ rW1, const float* __restrict__ rb1,
    int B)
{
    const int bn = blockIdx.x;            // 0..31 : module m=bn>>3, colbase=(bn&7)*64
    const int bm = blockIdx.y;            // row block of 64
    const int m  = bn >> 3;
    const int cb = (bn & 7) * 64;
    const float* W    = (m == 0) ? eW1 : (rW1 + (size_t)(m - 1) * S * Hd);
    const float* bias = (m == 0) ? eb1 : (rb1 + (size_t)(m - 1) * Hd);

    __shared__ float As[16][68];
    __shared__ float Bs[16][68];

    const int tid = threadIdx.x;
    const int tx = tid & 15;              // n quad (4 cols = 2 pairs)
    const int ty = tid >> 4;              // m quad (4 rows)

    u64 acc[4][2];                        // [m][n-pair]
    #pragma unroll
    for (int i = 0; i < 4; i++) { acc[i][0] = 0ull; acc[i][1] = 0ull; }

    const int rowBase = bm * 64;
    const int la_row = tid >> 2;          // 0..63
    const int la_q   = tid & 3;           // float4 index within 16-k chunk
    const int lw_k   = tid >> 4;          // 0..15
    const int lw_q   = tid & 15;          // 0..15

    for (int k0 = 0; k0 < S; k0 += 16) {
        float4 av = *(const float4*)&x[(size_t)(rowBase + la_row) * S + k0 + la_q * 4];
        float4 wv = *(const float4*)&W[(size_t)(k0 + lw_k) * Hd + cb + lw_q * 4];
        __syncthreads();
        As[la_q * 4 + 0][la_row] = av.x;
        As[la_q * 4 + 1][la_row] = av.y;
        As[la_q * 4 + 2][la_row] = av.z;
        As[la_q * 4 + 3][la_row] = av.w;
        *(float4*)&Bs[lw_k][lw_q * 4] = wv;
        __syncthreads();
        #pragma unroll
        for (int kk = 0; kk < 16; kk++) {
            float4 a = *(const float4*)&As[kk][ty * 4];
            float4 w = *(const float4*)&Bs[kk][tx * 4];
            u64 wp0 = pk2(w.x, w.y);
            u64 wp1 = pk2(w.z, w.w);
            float av4[4] = {a.x, a.y, a.z, a.w};
            #pragma unroll
            for (int i = 0; i < 4; i++) {
                u64 ad = pk2(av4[i], av4[i]);
                fma2(acc[i][0], ad, wp0);
                fma2(acc[i][1], ad, wp1);
            }
        }
    }

    float bv[4];
    #pragma unroll
    for (int j = 0; j < 4; j++) bv[j] = bias[cb + tx * 4 + j];

    #pragma unroll
    for (int i = 0; i < 4; i++) {
        int row = rowBase + ty * 4 + i;
        #pragma unroll
        for (int p = 0; p < 2; p++) {
            float2 v = upk(acc[i][p]);
            int col = cb + tx * 4 + 2 * p;
            g_H[((size_t)m * B + row) * Hd + col]     = tanhf(v.x + bv[2 * p]);
            g_H[((size_t)m * B + row) * Hd + col + 1] = tanhf(v.y + bv[2 * p + 1]);
        }
    }
}

// ---------------------------------------------------------------------------
// Kernel 2: tiled GEMM layer2. M-tile 32 rows, N = full module width (64 or 32)
// ---------------------------------------------------------------------------
template<int O>
__device__ __forceinline__ void k2_body(
    const float* __restrict__ Hb, const float* __restrict__ W2,
    const float* __restrict__ bias, float* __restrict__ outp,
    int B, float* sm)
{
    constexpr int TX = O / 4;             // threads along n (16 or 8)
    constexpr int RT = 32 * TX / 256;     // rows per thread (2 or 1)
    float* Hs = sm;                       // [32 k][36 m]
    float* Ws = sm + 32 * 36;             // [32 k][O+4]

    const int tid = threadIdx.x;
    const int rowBase = blockIdx.x * 32;
    const int tx = tid % TX;
    const int ty = tid / TX;

    const int h_row = tid >> 3;
    const int h_q   = tid & 7;

    float acc[RT][4];
    #pragma unroll
    for (int i = 0; i < RT; i++)
        #pragma unroll
        for (int j = 0; j < 4; j++) acc[i][j] = 0.0f;

    for (int k0 = 0; k0 < Hd; k0 += 32) {
        float4 hv = *(const float4*)&Hb[(size_t)(rowBase + h_row) * Hd + k0 + h_q * 4];
        float4 wv[2];
        #pragma unroll
        for (int it = 0; it < (8 * O) / 256; it++) {
            int i = tid + it * 256;
            int k  = i / TX;
            int n4 = i % TX;
            wv[it] = *(const float4*)&W2[(size_t)(k0 + k) * O + n4 * 4];
        }
        __syncthreads();
        Hs[(h_q * 4 + 0) * 36 + h_row] = hv.x;
        Hs[(h_q * 4 + 1) * 36 + h_row] = hv.y;
        Hs[(h_q * 4 + 2) * 36 + h_row] = hv.z;
        Hs[(h_q * 4 + 3) * 36 + h_row] = hv.w;
        #pragma unroll
        for (int it = 0; it < (8 * O) / 256; it++) {
            int i = tid + it * 256;
            int k  = i / TX;
            int n4 = i % TX;
            *(float4*)&Ws[k * (O + 4) + n4 * 4] = wv[it];
        }
        __syncthreads();
        #pragma unroll
        for (int kk = 0; kk < 32; kk++) {
            float a[RT];
            #pragma unroll
            for (int i = 0; i < RT; i++) a[i] = Hs[kk * 36 + ty * RT + i];
            float4 w = *(const float4*)&Ws[kk * (O + 4) + tx * 4];
            #pragma unroll
            for (int i = 0; i < RT; i++) {
                acc[i][0] += a[i] * w.x;
                acc[i][1] += a[i] * w.y;
                acc[i][2] += a[i] * w.z;
                acc[i][3] += a[i] * w.w;
            }
        }
    }

    float bv[4];
    #pragma unroll
    for (int j = 0; j < 4; j++) bv[j] = bias[tx * 4 + j];
    #pragma unroll
    for (int i = 0; i < RT; i++) {
        int row = rowBase + ty * RT + i;
        #pragma unroll
        for (int j = 0; j < 4; j++)
            outp[(size_t)row * O + tx * 4 + j] = acc[i][j] + bv[j];
    }
}

__global__ __launch_bounds__(256) void k2_all(
    const float* __restrict__ eW2, const float* __restrict__ eb2,
    const float* __restrict__ rW2, const float* __restrict__ rb2, int B)
{
    extern __shared__ float sm2[];
    if (blockIdx.y == 0) {
        k2_body<64>(g_H, eW2, eb2, g_e0, B, sm2);
    } else {
        int km = blockIdx.y - 1;
        k2_body<32>(g_H + (size_t)(1 + km) * B * Hd,
                    rW2 + (size_t)km * Hd * R, rb2 + km * R,
                    g_r + (size_t)km * B * R, B, sm2);
    }
}

// ---------------------------------------------------------------------------
// Kernel 3: one CTA per batch. Single pass over tpr[b] builds
//   A_k[e,f] = sum_r r_k[r] * tpr[b,e,r,f]   (k=0,1,2) in smem via f32x2,
// then the sequential i1/i2/i3 chain with layernorm, then @Z.
// ROLLED j-loop + batched-8 loads: keeps 6 u64 accs live, no spills, MLP>=8.
// ---------------------------------------------------------------------------
__global__ __launch_bounds__(256, 4) void k3_main(
    const float* __restrict__ tpr,
    const float* __restrict__ ln_g, const float* __restrict__ ln_b,
    const float* __restrict__ Z,
    float* __restrict__ out, int B)
{
    extern __shared__ float sm[];
    float*  sA   = sm;                        // 3*64*64 = 12288 floats
    float*  scur = sA + 3 * E * E;            // 64
    float*  ssum = scur + E;                  // 64
    float2* srv2 = (float2*)(ssum + E);       // 96 float2 (duplicated coefs)
    float*  sred = (float*)(srv2 + 96);       // 4

    const int b   = blockIdx.x;
    const int tid = threadIdx.x;

    if (tid < 96) {
        float v = g_r[((size_t)(tid >> 5) * B + b) * R + (tid & 31)];
        srv2[tid] = make_float2(v, v);
    }
    if (tid < E) { scur[tid] = g_e0[(size_t)b * E + tid]; ssum[tid] = 0.0f; }
    __syncthreads();

    // --- A pass: read tpr[b] once (512 KB) ---
    const int f4 = tid & 15;
    const int eg = tid >> 4;
    #pragma unroll 1
    for (int j = 0; j < 4; j++) {
        const int e = eg + j * 16;
        const float4* p = (const float4*)tpr + ((size_t)b * E + e) * (R * 16) + f4;
        u64 a00 = 0, a01 = 0, a10 = 0, a11 = 0, a20 = 0, a21 = 0;
        #pragma unroll 1
        for (int rb = 0; rb < 4; rb++) {
            float4 buf[8];
            #pragma unroll
            for (int u = 0; u < 8; u++)
                buf[u] = __ldcs(&p[(size_t)(rb * 8 + u) * 16]);
            #pragma unroll
            for (int u = 0; u < 8; u++) {
                const int r = rb * 8 + u;
                u64 t01 = pk2(buf[u].x, buf[u].y);
                u64 t23 = pk2(buf[u].z, buf[u].w);
                float2 c0f = srv2[r], c1f = srv2[32 + r], c2f = srv2[64 + r];
                u64 c0 = *(u64*)&c0f;
                u64 c1 = *(u64*)&c1f;
                u64 c2 = *(u64*)&c2f;
                fma2(a00, c0, t01); fma2(a01, c0, t23);
                fma2(a10, c1, t01); fma2(a11, c1, t23);
                fma2(a20, c2, t01); fma2(a21, c2, t23);
            }
        }
        *(float2*)&sA[(0 * E + e) * E + f4 * 4]     = upk(a00);
        *(float2*)&sA[(0 * E + e) * E + f4 * 4 + 2] = upk(a01);
        *(float2*)&sA[(1 * E + e) * E + f4 * 4]     = upk(a10);
        *(float2*)&sA[(1 * E + e) * E + f4 * 4 + 2] = upk(a11);
        *(float2*)&sA[(2 * E + e) * E + f4 * 4]     = upk(a20);
        *(float2*)&sA[(2 * E + e) * E + f4 * 4 + 2] = upk(a21);
    }
    __syncthreads();

    // --- chain: i_{k+1} = LN( cur @ A_k ) ; ssum += i ---
    for (int step = 0; step < 3; step++) {
        float sval = 0.0f;
        if (tid < E) {
            const float* Ak = &sA[step * E * E];
            #pragma unroll 16
            for (int e = 0; e < E; e++) sval += scur[e] * Ak[e * E + tid];
            float s1 = sval, s2 = sval * sval;
            #pragma unroll
            for (int o = 16; o; o >>= 1) {
                s1 += __shfl_xor_sync(0xffffffffu, s1, o);
                s2 += __shfl_xor_sync(0xffffffffu, s2, o);
            }
            if ((tid & 31) == 0) { sred[(tid >> 5) * 2] = s1; sred[(tid >> 5) * 2 + 1] = s2; }
        }
        __syncthreads();
        if (tid < E) {
            float s1 = sred[0] + sred[2];
            float s2 = sred[1] + sred[3];
            float mu  = s1 * (1.0f / 64.0f);
            float var = s2 * (1.0f / 64.0f) - mu * mu;
            float inv = rsqrtf(var + 1e-6f);
            float iv  = ln_g[step * E + tid] * (sval - mu) * inv + ln_b[step * E + tid];
            scur[tid] = iv;
            ssum[tid] += iv;
        }
        __syncthreads();
    }

    // --- out[b,:] = step_sum @ Z ---
    if (tid < L) {
        float acc = 0.0f;
        #pragma unroll 8
        for (int f = 0; f < E; f++) acc += ssum[f] * Z[f * L + tid];
        out[(size_t)b * L + tid] = acc;
    }
}

// ---------------------------------------------------------------------------
extern "C" void kernel_launch(void* const* d_in, const int* in_sizes, int n_in,
                              void* d_out, int out_size)
{
    const float* x    = (const float*)d_in[0];
    const float* tpr  = (const float*)d_in[1];
    const float* eW1  = (const float*)d_in[2];
    const float* eb1  = (const float*)d_in[3];
    const float* eW2  = (const float*)d_in[4];
    const float* eb2  = (const float*)d_in[5];
    const float* rW1  = (const float*)d_in[6];
    const float* rb1  = (const float*)d_in[7];
    const float* rW2  = (const float*)d_in[8];
    const float* rb2  = (const float*)d_in[9];
    const float* ln_g = (const float*)d_in[10];
    const float* ln_b = (const float*)d_in[11];
    const float* Z    = (const float*)d_in[12];
    float* out = (float*)d_out;

    int B = in_sizes[0] / S;   // 1024

    dim3 g1(32, B / 64);
    k1_gemm_tanh<<<g1, 256>>>(x, eW1, eb1, rW1, rb1, B);

    dim3 g2(B / 32, 4);
    size_t smem2 = (size_t)(32 * 36 + 32 * 68) * sizeof(float);
    k2_all<<<g2, 256, smem2>>>(eW2, eb2, rW2, rb2, B);

    size_t smem3 = (size_t)(3 * E * E + E + E) * sizeof(float)
                 + 96 * sizeof(float2) + 8 * sizeof(float);
    cudaFuncSetAttribute(k3_main, cudaFuncAttributeMaxDynamicSharedMemorySize, (int)smem3);
    k3_main<<<B, 256, smem3>>>(tpr, ln_g, ln_b, Z, out, B);
}

// round 4
// speedup vs baseline: 1.6183x; 1.0332x over previous
#include <cuda_runtime.h>
#include <math.h>

#define S   256
#define Hd  512
#define E   64
#define R   32
#define L   9
#define BMAX 1024

typedef unsigned long long u64;

// Scratch (device globals; no allocation allowed)
__device__ float g_H[4 * BMAX * Hd];     // tanh(x@W1+b1) for modules {e0, r0, r1, r2}
__device__ float g_e02[2 * BMAX * E];    // split-K partials of e0
__device__ float g_r2[2 * 3 * BMAX * R]; // split-K partials of r

// ---------------------------------------------------------------------------
// Packed f32x2 helpers (Blackwell FFMA2 — ptxas never emits this from C++)
// ---------------------------------------------------------------------------
__device__ __forceinline__ u64 pk2(float x, float y) {
    u64 r;
    asm("mov.b64 %0, {%1, %2};" : "=l"(r) : "f"(x), "f"(y));
    return r;
}
__device__ __forceinline__ void fma2(u64& d, u64 a, u64 b) {
    asm("fma.rn.f32x2 %0, %1, %2, %0;" : "+l"(d) : "l"(a), "l"(b));
}
__device__ __forceinline__ float2 upk(u64 v) {
    float2 f;
    asm("mov.b64 {%0, %1}, %2;" : "=f"(f.x), "=f"(f.y) : "l"(v));
    return f;
}

// ---------------------------------------------------------------------------
// Kernel 1: H = tanh(x @ W1 + b1) ; GEMM M=B, N=4*512, K=256
// 32x64 tiles, 128 threads, 4x4 micro via FFMA2, double-buffered smem
// (one __syncthreads per k-chunk), grid = 1024 CTAs.
// ---------------------------------------------------------------------------
__global__ __launch_bounds__(128) void k1_gemm_tanh(
    const float* __restrict__ x,
    const float* __restrict__ eW1, const float* __restrict__ eb1,
    const float* __restrict__ rW1, const float* __restrict__ rb1,
    int B)
{
    const int bn = blockIdx.x;            // 0..31 : module m=bn>>3, colbase=(bn&7)*64
    const int bm = blockIdx.y;            // row block of 32
    const int m  = bn >> 3;
    const int cb = (bn & 7) * 64;
    const float* W    = (m == 0) ? eW1 : (rW1 + (size_t)(m - 1) * S * Hd);
    const float* bias = (m == 0) ? eb1 : (rb1 + (size_t)(m - 1) * Hd);

    __shared__ float As[2][16][36];   // [buf][k][m]
    __shared__ float Bs[2][16][68];   // [buf][k][n]

    const int tid = threadIdx.x;
    const int tx = tid & 15;              // n quad
    const int ty = tid >> 4;              // m quad (0..7)
    const int rowBase = bm * 32;

    const int a_row = tid >> 2;           // 0..31
    const int a_q   = tid & 3;
    const int w_k   = tid >> 4;           // 0..7 (+8 for second)
    const int w_q   = tid & 15;

    u64 acc[4][2];
    #pragma unroll
    for (int i = 0; i < 4; i++) { acc[i][0] = 0ull; acc[i][1] = 0ull; }

    float4 av, wv0, wv1;
    av  = *(const float4*)&x[(size_t)(rowBase + a_row) * S + a_q * 4];
    wv0 = *(const float4*)&W[(size_t)(w_k)     * Hd + cb + w_q * 4];
    wv1 = *(const float4*)&W[(size_t)(w_k + 8) * Hd + cb + w_q * 4];

    int buf = 0;
    As[0][a_q * 4 + 0][a_row] = av.x;
    As[0][a_q * 4 + 1][a_row] = av.y;
    As[0][a_q * 4 + 2][a_row] = av.z;
    As[0][a_q * 4 + 3][a_row] = av.w;
    *(float4*)&Bs[0][w_k][w_q * 4]     = wv0;
    *(float4*)&Bs[0][w_k + 8][w_q * 4] = wv1;
    __syncthreads();

    for (int c = 0; c < 16; c++) {
        if (c < 15) {
            const int k0 = (c + 1) * 16;
            av  = *(const float4*)&x[(size_t)(rowBase + a_row) * S + k0 + a_q * 4];
            wv0 = *(const float4*)&W[(size_t)(k0 + w_k)     * Hd + cb + w_q * 4];
            wv1 = *(const float4*)&W[(size_t)(k0 + w_k + 8) * Hd + cb + w_q * 4];
        }
        #pragma unroll
        for (int kk = 0; kk < 16; kk++) {
            float4 a = *(const float4*)&As[buf][kk][ty * 4];
            float4 w = *(const float4*)&Bs[buf][kk][tx * 4];
            u64 wp0 = pk2(w.x, w.y);
            u64 wp1 = pk2(w.z, w.w);
            float av4[4] = {a.x, a.y, a.z, a.w};
            #pragma unroll
            for (int i = 0; i < 4; i++) {
                u64 ad = pk2(av4[i], av4[i]);
                fma2(acc[i][0], ad, wp0);
                fma2(acc[i][1], ad, wp1);
            }
        }
        if (c < 15) {
            const int nb = buf ^ 1;
            As[nb][a_q * 4 + 0][a_row] = av.x;
            As[nb][a_q * 4 + 1][a_row] = av.y;
            As[nb][a_q * 4 + 2][a_row] = av.z;
            As[nb][a_q * 4 + 3][a_row] = av.w;
            *(float4*)&Bs[nb][w_k][w_q * 4]     = wv0;
            *(float4*)&Bs[nb][w_k + 8][w_q * 4] = wv1;
            __syncthreads();
            buf = nb;
        }
    }

    float bv[4];
    #pragma unroll
    for (int j = 0; j < 4; j++) bv[j] = bias[cb + tx * 4 + j];

    #pragma unroll
    for (int i = 0; i < 4; i++) {
        int row = rowBase + ty * 4 + i;
        #pragma unroll
        for (int p = 0; p < 2; p++) {
            float2 v = upk(acc[i][p]);
            int col = cb + tx * 4 + 2 * p;
            g_H[((size_t)m * B + row) * Hd + col]     = tanhf(v.x + bv[2 * p]);
            g_H[((size_t)m * B + row) * Hd + col + 1] = tanhf(v.y + bv[2 * p + 1]);
        }
    }
}

// ---------------------------------------------------------------------------
// Kernel 2: layer2 GEMM with split-K (2 chunks of 256). Partials summed in k3.
// ---------------------------------------------------------------------------
template<int O>
__device__ __forceinline__ void k2_body(
    const float* __restrict__ Hb, const float* __restrict__ W2,
    const float* __restrict__ bias, float* __restrict__ outp,
    int B, int kbeg, float* sm)
{
    constexpr int TX = O / 4;             // threads along n (16 or 8)
    constexpr int RT = 32 * TX / 256;     // rows per thread (2 or 1)
    float* Hs = sm;                       // [32 k][36 m]
    float* Ws = sm + 32 * 36;             // [32 k][O+4]

    const int tid = threadIdx.x;
    const int rowBase = blockIdx.x * 32;
    const int tx = tid % TX;
    const int ty = tid / TX;

    const int h_row = tid >> 3;
    const int h_q   = tid & 7;

    float acc[RT][4];
    #pragma unroll
    for (int i = 0; i < RT; i++)
        #pragma unroll
        for (int j = 0; j < 4; j++) acc[i][j] = 0.0f;

    for (int k0 = kbeg; k0 < kbeg + 256; k0 += 32) {
        float4 hv = *(const float4*)&Hb[(size_t)(rowBase + h_row) * Hd + k0 + h_q * 4];
        float4 wv[2];
        #pragma unroll
        for (int it = 0; it < (8 * O) / 256; it++) {
            int i = tid + it * 256;
            int k  = i / TX;
            int n4 = i % TX;
            wv[it] = *(const float4*)&W2[(size_t)(k0 + k) * O + n4 * 4];
        }
        __syncthreads();
        Hs[(h_q * 4 + 0) * 36 + h_row] = hv.x;
        Hs[(h_q * 4 + 1) * 36 + h_row] = hv.y;
        Hs[(h_q * 4 + 2) * 36 + h_row] = hv.z;
        Hs[(h_q * 4 + 3) * 36 + h_row] = hv.w;
        #pragma unroll
        for (int it = 0; it < (8 * O) / 256; it++) {
            int i = tid + it * 256;
            int k  = i / TX;
            int n4 = i % TX;
            *(float4*)&Ws[k * (O + 4) + n4 * 4] = wv[it];
        }
        __syncthreads();
        #pragma unroll
        for (int kk = 0; kk < 32; kk++) {
            float a[RT];
            #pragma unroll
            for (int i = 0; i < RT; i++) a[i] = Hs[kk * 36 + ty * RT + i];
            float4 w = *(const float4*)&Ws[kk * (O + 4) + tx * 4];
            #pragma unroll
            for (int i = 0; i < RT; i++) {
                acc[i][0] += a[i] * w.x;
                acc[i][1] += a[i] * w.y;
                acc[i][2] += a[i] * w.z;
                acc[i][3] += a[i] * w.w;
            }
        }
    }

    float bv[4];
    #pragma unroll
    for (int j = 0; j < 4; j++) bv[j] = bias ? bias[tx * 4 + j] : 0.0f;
    #pragma unroll
    for (int i = 0; i < RT; i++) {
        int row = rowBase + ty * RT + i;
        #pragma unroll
        for (int j = 0; j < 4; j++)
            outp[(size_t)row * O + tx * 4 + j] = acc[i][j] + bv[j];
    }
}

__global__ __launch_bounds__(256) void k2_all(
    const float* __restrict__ eW2, const float* __restrict__ eb2,
    const float* __restrict__ rW2, const float* __restrict__ rb2, int B)
{
    extern __shared__ float sm2[];
    const int kz   = blockIdx.z;
    const int kbeg = kz * 256;
    if (blockIdx.y == 0) {
        k2_body<64>(g_H, eW2, kz ? nullptr : eb2,
                    g_e02 + (size_t)kz * B * E, B, kbeg, sm2);
    } else {
        int km = blockIdx.y - 1;
        k2_body<32>(g_H + (size_t)(1 + km) * B * Hd,
                    rW2 + (size_t)km * Hd * R, kz ? nullptr : (rb2 + km * R),
                    g_r2 + (size_t)kz * 3 * B * R + (size_t)km * B * R,
                    B, kbeg, sm2);
    }
}

// ---------------------------------------------------------------------------
// Kernel 3: one CTA per batch. Single pass over tpr[b] builds
//   A_k[e,f] = sum_r r_k[r] * tpr[b,e,r,f]   (k=0,1,2) in smem via f32x2,
// then the sequential i1/i2/i3 chain with layernorm, then @Z.
// ---------------------------------------------------------------------------
__global__ __launch_bounds__(256, 4) void k3_main(
    const float* __restrict__ tpr,
    const float* __restrict__ ln_g, const float* __restrict__ ln_b,
    const float* __restrict__ Z,
    float* __restrict__ out, int B)
{
    extern __shared__ float sm[];
    float*  sA   = sm;                        // 3*64*64 = 12288 floats
    float*  scur = sA + 3 * E * E;            // 64
    float*  ssum = scur + E;                  // 64
    float2* srv2 = (float2*)(ssum + E);       // 96 float2 (duplicated coefs)
    float*  sred = (float*)(srv2 + 96);       // 4

    const int b   = blockIdx.x;
    const int tid = threadIdx.x;

    if (tid < 96) {
        const int k = tid >> 5, j = tid & 31;
        size_t idx = ((size_t)k * B + b) * R + j;
        float v = g_r2[idx] + g_r2[(size_t)3 * B * R + idx];
        srv2[tid] = make_float2(v, v);
    }
    if (tid < E) {
        scur[tid] = g_e02[(size_t)b * E + tid] + g_e02[(size_t)B * E + (size_t)b * E + tid];
        ssum[tid] = 0.0f;
    }
    __syncthreads();

    // --- A pass: read tpr[b] once (512 KB) ---
    const int f4 = tid & 15;
    const int eg = tid >> 4;
    #pragma unroll 1
    for (int j = 0; j < 4; j++) {
        const int e = eg + j * 16;
        const float4* p = (const float4*)tpr + ((size_t)b * E + e) * (R * 16) + f4;
        u64 a00 = 0, a01 = 0, a10 = 0, a11 = 0, a20 = 0, a21 = 0;
        #pragma unroll 1
        for (int rb = 0; rb < 4; rb++) {
            float4 buf[8];
            #pragma unroll
            for (int u = 0; u < 8; u++)
                buf[u] = __ldcs(&p[(size_t)(rb * 8 + u) * 16]);
            #pragma unroll
            for (int u = 0; u < 8; u++) {
                const int r = rb * 8 + u;
                u64 t01 = pk2(buf[u].x, buf[u].y);
                u64 t23 = pk2(buf[u].z, buf[u].w);
                float2 c0f = srv2[r], c1f = srv2[32 + r], c2f = srv2[64 + r];
                u64 c0 = *(u64*)&c0f;
                u64 c1 = *(u64*)&c1f;
                u64 c2 = *(u64*)&c2f;
                fma2(a00, c0, t01); fma2(a01, c0, t23);
                fma2(a10, c1, t01); fma2(a11, c1, t23);
                fma2(a20, c2, t01); fma2(a21, c2, t23);
            }
        }
        *(float2*)&sA[(0 * E + e) * E + f4 * 4]     = upk(a00);
        *(float2*)&sA[(0 * E + e) * E + f4 * 4 + 2] = upk(a01);
        *(float2*)&sA[(1 * E + e) * E + f4 * 4]     = upk(a10);
        *(float2*)&sA[(1 * E + e) * E + f4 * 4 + 2] = upk(a11);
        *(float2*)&sA[(2 * E + e) * E + f4 * 4]     = upk(a20);
        *(float2*)&sA[(2 * E + e) * E + f4 * 4 + 2] = upk(a21);
    }
    __syncthreads();

    // --- chain: i_{k+1} = LN( cur @ A_k ) ; ssum += i ---
    for (int step = 0; step < 3; step++) {
        float sval = 0.0f;
        if (tid < E) {
            const float* Ak = &sA[step * E * E];
            #pragma unroll 16
            for (int e = 0; e < E; e++) sval += scur[e] * Ak[e * E + tid];
            float s1 = sval, s2 = sval * sval;
            #pragma unroll
            for (int o = 16; o; o >>= 1) {
                s1 += __shfl_xor_sync(0xffffffffu, s1, o);
                s2 += __shfl_xor_sync(0xffffffffu, s2, o);
            }
            if ((tid & 31) == 0) { sred[(tid >> 5) * 2] = s1; sred[(tid >> 5) * 2 + 1] = s2; }
        }
        __syncthreads();
        if (tid < E) {
            float s1 = sred[0] + sred[2];
            float s2 = sred[1] + sred[3];
            float mu  = s1 * (1.0f / 64.0f);
            float var = s2 * (1.0f / 64.0f) - mu * mu;
            float inv = rsqrtf(var + 1e-6f);
            float iv  = ln_g[step * E + tid] * (sval - mu) * inv + ln_b[step * E + tid];
            scur[tid] = iv;
            ssum[tid] += iv;
        }
        __syncthreads();
    }

    // --- out[b,:] = step_sum @ Z ---
    if (tid < L) {
        float acc = 0.0f;
        #pragma unroll 8
        for (int f = 0; f < E; f++) acc += ssum[f] * Z[f * L + tid];
        out[(size_t)b * L + tid] = acc;
    }
}

// ---------------------------------------------------------------------------
extern "C" void kernel_launch(void* const* d_in, const int* in_sizes, int n_in,
                              void* d_out, int out_size)
{
    const float* x    = (const float*)d_in[0];
    const float* tpr  = (const float*)d_in[1];
    const float* eW1  = (const float*)d_in[2];
    const float* eb1  = (const float*)d_in[3];
    const float* eW2  = (const float*)d_in[4];
    const float* eb2  = (const float*)d_in[5];
    const float* rW1  = (const float*)d_in[6];
    const float* rb1  = (const float*)d_in[7];
    const float* rW2  = (const float*)d_in[8];
    const float* rb2  = (const float*)d_in[9];
    const float* ln_g = (const float*)d_in[10];
    const float* ln_b = (const float*)d_in[11];
    const float* Z    = (const float*)d_in[12];
    float* out = (float*)d_out;

    int B = in_sizes[0] / S;   // 1024

    dim3 g1(32, B / 32);
    k1_gemm_tanh<<<g1, 128>>>(x, eW1, eb1, rW1, rb1, B);

    dim3 g2(B / 32, 4, 2);
    size_t smem2 = (size_t)(32 * 36 + 32 * 68) * sizeof(float);
    k2_all<<<g2, 256, smem2>>>(eW2, eb2, rW2, rb2, B);

    size_t smem3 = (size_t)(3 * E * E + E + E) * sizeof(float)
                 + 96 * sizeof(float2) + 8 * sizeof(float);
    cudaFuncSetAttribute(k3_main, cudaFuncAttributeMaxDynamicSharedMemorySize, (int)smem3);
    k3_main<<<B, 256, smem3>>>(tpr, ln_g, ln_b, Z, out, B);
}

// round 5
// speedup vs baseline: 1.6495x; 1.0193x over previous
#include <cuda_runtime.h>
#include <math.h>

#define S   256
#define Hd  512
#define E   64
#define R   32
#define L   9
#define BMAX 1024

typedef unsigned long long u64;

// Scratch (device globals; no allocation allowed)
__device__ float g_H[4 * BMAX * Hd];     // tanh(x@W1+b1) for modules {e0, r0, r1, r2}
__device__ float g_e02[2 * BMAX * E];    // split-K partials of e0
__device__ float g_r2[2 * 3 * BMAX * R]; // split-K partials of r
__device__ float g_A[(size_t)BMAX * 3 * E * E]; // A_k[b][k][e][f]

// ---------------------------------------------------------------------------
// Packed f32x2 helpers (Blackwell FFMA2 — ptxas never emits this from C++)
// ---------------------------------------------------------------------------
__device__ __forceinline__ u64 pk2(float x, float y) {
    u64 r;
    asm("mov.b64 %0, {%1, %2};" : "=l"(r) : "f"(x), "f"(y));
    return r;
}
__device__ __forceinline__ void fma2(u64& d, u64 a, u64 b) {
    asm("fma.rn.f32x2 %0, %1, %2, %0;" : "+l"(d) : "l"(a), "l"(b));
}
__device__ __forceinline__ float2 upk(u64 v) {
    float2 f;
    asm("mov.b64 {%0, %1}, %2;" : "=f"(f.x), "=f"(f.y) : "l"(v));
    return f;
}

// ---------------------------------------------------------------------------
// Kernel 1: H = tanh(x @ W1 + b1) ; GEMM M=B, N=4*512, K=256
// 32x64 tiles, 128 threads, 4x4 micro via FFMA2, double-buffered smem.
// ---------------------------------------------------------------------------
__global__ __launch_bounds__(128) void k1_gemm_tanh(
    const float* __restrict__ x,
    const float* __restrict__ eW1, const float* __restrict__ eb1,
    const float* __restrict__ rW1, const float* __restrict__ rb1,
    int B)
{
    const int bn = blockIdx.x;
    const int bm = blockIdx.y;
    const int m  = bn >> 3;
    const int cb = (bn & 7) * 64;
    const float* W    = (m == 0) ? eW1 : (rW1 + (size_t)(m - 1) * S * Hd);
    const float* bias = (m == 0) ? eb1 : (rb1 + (size_t)(m - 1) * Hd);

    __shared__ float As[2][16][36];
    __shared__ float Bs[2][16][68];

    const int tid = threadIdx.x;
    const int tx = tid & 15;
    const int ty = tid >> 4;
    const int rowBase = bm * 32;

    const int a_row = tid >> 2;
    const int a_q   = tid & 3;
    const int w_k   = tid >> 4;
    const int w_q   = tid & 15;

    u64 acc[4][2];
    #pragma unroll
    for (int i = 0; i < 4; i++) { acc[i][0] = 0ull; acc[i][1] = 0ull; }

    float4 av, wv0, wv1;
    av  = *(const float4*)&x[(size_t)(rowBase + a_row) * S + a_q * 4];
    wv0 = *(const float4*)&W[(size_t)(w_k)     * Hd + cb + w_q * 4];
    wv1 = *(const float4*)&W[(size_t)(w_k + 8) * Hd + cb + w_q * 4];

    int buf = 0;
    As[0][a_q * 4 + 0][a_row] = av.x;
    As[0][a_q * 4 + 1][a_row] = av.y;
    As[0][a_q * 4 + 2][a_row] = av.z;
    As[0][a_q * 4 + 3][a_row] = av.w;
    *(float4*)&Bs[0][w_k][w_q * 4]     = wv0;
    *(float4*)&Bs[0][w_k + 8][w_q * 4] = wv1;
    __syncthreads();

    for (int c = 0; c < 16; c++) {
        if (c < 15) {
            const int k0 = (c + 1) * 16;
            av  = *(const float4*)&x[(size_t)(rowBase + a_row) * S + k0 + a_q * 4];
            wv0 = *(const float4*)&W[(size_t)(k0 + w_k)     * Hd + cb + w_q * 4];
            wv1 = *(const float4*)&W[(size_t)(k0 + w_k + 8) * Hd + cb + w_q * 4];
        }
        #pragma unroll
        for (int kk = 0; kk < 16; kk++) {
            float4 a = *(const float4*)&As[buf][kk][ty * 4];
            float4 w = *(const float4*)&Bs[buf][kk][tx * 4];
            u64 wp0 = pk2(w.x, w.y);
            u64 wp1 = pk2(w.z, w.w);
            float av4[4] = {a.x, a.y, a.z, a.w};
            #pragma unroll
            for (int i = 0; i < 4; i++) {
                u64 ad = pk2(av4[i], av4[i]);
                fma2(acc[i][0], ad, wp0);
                fma2(acc[i][1], ad, wp1);
            }
        }
        if (c < 15) {
            const int nb = buf ^ 1;
            As[nb][a_q * 4 + 0][a_row] = av.x;
            As[nb][a_q * 4 + 1][a_row] = av.y;
            As[nb][a_q * 4 + 2][a_row] = av.z;
            As[nb][a_q * 4 + 3][a_row] = av.w;
            *(float4*)&Bs[nb][w_k][w_q * 4]     = wv0;
            *(float4*)&Bs[nb][w_k + 8][w_q * 4] = wv1;
            __syncthreads();
            buf = nb;
        }
    }

    float bv[4];
    #pragma unroll
    for (int j = 0; j < 4; j++) bv[j] = bias[cb + tx * 4 + j];

    #pragma unroll
    for (int i = 0; i < 4; i++) {
        int row = rowBase + ty * 4 + i;
        #pragma unroll
        for (int p = 0; p < 2; p++) {
            float2 v = upk(acc[i][p]);
            int col = cb + tx * 4 + 2 * p;
            g_H[((size_t)m * B + row) * Hd + col]     = tanhf(v.x + bv[2 * p]);
            g_H[((size_t)m * B + row) * Hd + col + 1] = tanhf(v.y + bv[2 * p + 1]);
        }
    }
}

// ---------------------------------------------------------------------------
// Kernel 2: layer2 GEMM with split-K (2 chunks of 256). Partials summed later.
// ---------------------------------------------------------------------------
template<int O>
__device__ __forceinline__ void k2_body(
    const float* __restrict__ Hb, const float* __restrict__ W2,
    const float* __restrict__ bias, float* __restrict__ outp,
    int B, int kbeg, float* sm)
{
    constexpr int TX = O / 4;
    constexpr int RT = 32 * TX / 256;
    float* Hs = sm;
    float* Ws = sm + 32 * 36;

    const int tid = threadIdx.x;
    const int rowBase = blockIdx.x * 32;
    const int tx = tid % TX;
    const int ty = tid / TX;

    const int h_row = tid >> 3;
    const int h_q   = tid & 7;

    float acc[RT][4];
    #pragma unroll
    for (int i = 0; i < RT; i++)
        #pragma unroll
        for (int j = 0; j < 4; j++) acc[i][j] = 0.0f;

    for (int k0 = kbeg; k0 < kbeg + 256; k0 += 32) {
        float4 hv = *(const float4*)&Hb[(size_t)(rowBase + h_row) * Hd + k0 + h_q * 4];
        float4 wv[2];
        #pragma unroll
        for (int it = 0; it < (8 * O) / 256; it++) {
            int i = tid + it * 256;
            int k  = i / TX;
            int n4 = i % TX;
            wv[it] = *(const float4*)&W2[(size_t)(k0 + k) * O + n4 * 4];
        }
        __syncthreads();
        Hs[(h_q * 4 + 0) * 36 + h_row] = hv.x;
        Hs[(h_q * 4 + 1) * 36 + h_row] = hv.y;
        Hs[(h_q * 4 + 2) * 36 + h_row] = hv.z;
        Hs[(h_q * 4 + 3) * 36 + h_row] = hv.w;
        #pragma unroll
        for (int it = 0; it < (8 * O) / 256; it++) {
            int i = tid + it * 256;
            int k  = i / TX;
            int n4 = i % TX;
            *(float4*)&Ws[k * (O + 4) + n4 * 4] = wv[it];
        }
        __syncthreads();
        #pragma unroll
        for (int kk = 0; kk < 32; kk++) {
            float a[RT];
            #pragma unroll
            for (int i = 0; i < RT; i++) a[i] = Hs[kk * 36 + ty * RT + i];
            float4 w = *(const float4*)&Ws[kk * (O + 4) + tx * 4];
            #pragma unroll
            for (int i = 0; i < RT; i++) {
                acc[i][0] += a[i] * w.x;
                acc[i][1] += a[i] * w.y;
                acc[i][2] += a[i] * w.z;
                acc[i][3] += a[i] * w.w;
            }
        }
    }

    float bv[4];
    #pragma unroll
    for (int j = 0; j < 4; j++) bv[j] = bias ? bias[tx * 4 + j] : 0.0f;
    #pragma unroll
    for (int i = 0; i < RT; i++) {
        int row = rowBase + ty * RT + i;
        #pragma unroll
        for (int j = 0; j < 4; j++)
            outp[(size_t)row * O + tx * 4 + j] = acc[i][j] + bv[j];
    }
}

__global__ __launch_bounds__(256) void k2_all(
    const float* __restrict__ eW2, const float* __restrict__ eb2,
    const float* __restrict__ rW2, const float* __restrict__ rb2, int B)
{
    extern __shared__ float sm2[];
    const int kz   = blockIdx.z;
    const int kbeg = kz * 256;
    if (blockIdx.y == 0) {
        k2_body<64>(g_H, eW2, kz ? nullptr : eb2,
                    g_e02 + (size_t)kz * B * E, B, kbeg, sm2);
    } else {
        int km = blockIdx.y - 1;
        k2_body<32>(g_H + (size_t)(1 + km) * B * Hd,
                    rW2 + (size_t)km * Hd * R, kz ? nullptr : (rb2 + km * R),
                    g_r2 + (size_t)kz * 3 * B * R + (size_t)km * B * R,
                    B, kbeg, sm2);
    }
}

// ---------------------------------------------------------------------------
// Kernel 3a: pure streaming contraction. One CTA per (batch, e-quarter of 16).
// 256 threads = (e_local 16) x (f4 16). Tiny smem -> high occupancy.
//   A_k[b][e][f] = sum_r r_k[b][r] * tpr[b,e,r,f]  -> g_A
// ---------------------------------------------------------------------------
__global__ __launch_bounds__(256) void k3a_contract(
    const float* __restrict__ tpr, int B)
{
    __shared__ float2 srv2[96];

    const int b = blockIdx.x >> 2;
    const int q = blockIdx.x & 3;
    const int tid = threadIdx.x;

    if (tid < 96) {
        const int k = tid >> 5, j = tid & 31;
        size_t idx = ((size_t)k * B + b) * R + j;
        float v = g_r2[idx] + g_r2[(size_t)3 * B * R + idx];
        srv2[tid] = make_float2(v, v);
    }
    __syncthreads();

    const int e  = q * 16 + (tid >> 4);
    const int f4 = tid & 15;
    const float4* p = (const float4*)tpr + ((size_t)b * E + e) * (R * 16) + f4;

    u64 a00 = 0, a01 = 0, a10 = 0, a11 = 0, a20 = 0, a21 = 0;
    #pragma unroll 1
    for (int rb = 0; rb < 4; rb++) {
        float4 buf[8];
        #pragma unroll
        for (int u = 0; u < 8; u++)
            buf[u] = __ldcs(&p[(size_t)(rb * 8 + u) * 16]);
        #pragma unroll
        for (int u = 0; u < 8; u++) {
            const int r = rb * 8 + u;
            u64 t01 = pk2(buf[u].x, buf[u].y);
            u64 t23 = pk2(buf[u].z, buf[u].w);
            float2 c0f = srv2[r], c1f = srv2[32 + r], c2f = srv2[64 + r];
            u64 c0 = *(u64*)&c0f;
            u64 c1 = *(u64*)&c1f;
            u64 c2 = *(u64*)&c2f;
            fma2(a00, c0, t01); fma2(a01, c0, t23);
            fma2(a10, c1, t01); fma2(a11, c1, t23);
            fma2(a20, c2, t01); fma2(a21, c2, t23);
        }
    }

    float* Ab = g_A + (size_t)b * 3 * E * E;
    float2 v0, v1;
    v0 = upk(a00); v1 = upk(a01);
    *(float4*)&Ab[(0 * E + e) * E + f4 * 4] = make_float4(v0.x, v0.y, v1.x, v1.y);
    v0 = upk(a10); v1 = upk(a11);
    *(float4*)&Ab[(1 * E + e) * E + f4 * 4] = make_float4(v0.x, v0.y, v1.x, v1.y);
    v0 = upk(a20); v1 = upk(a21);
    *(float4*)&Ab[(2 * E + e) * E + f4 * 4] = make_float4(v0.x, v0.y, v1.x, v1.y);
}

// ---------------------------------------------------------------------------
// Kernel 3b: chain. One CTA per batch: stage A (48KB, L2-resident) to smem,
// run LN chain, project with Z.
// ---------------------------------------------------------------------------
__global__ __launch_bounds__(256, 4) void k3b_chain(
    const float* __restrict__ ln_g, const float* __restrict__ ln_b,
    const float* __restrict__ Z,
    float* __restrict__ out, int B)
{
    extern __shared__ float sm[];
    float* sA   = sm;                 // 3*64*64
    float* scur = sA + 3 * E * E;     // 64
    float* ssum = scur + E;           // 64
    float* sred = ssum + E;           // 4

    const int b   = blockIdx.x;
    const int tid = threadIdx.x;

    // stage all 3 A matrices: 12288 floats = 3072 float4, 12 per thread
    {
        const float4* src = (const float4*)(g_A + (size_t)b * 3 * E * E);
        float4* dst = (float4*)sA;
        #pragma unroll
        for (int i = 0; i < 12; i++)
            dst[tid + i * 256] = __ldg(&src[tid + i * 256]);
    }
    if (tid < E) {
        scur[tid] = g_e02[(size_t)b * E + tid] + g_e02[(size_t)B * E + (size_t)b * E + tid];
        ssum[tid] = 0.0f;
    }
    __syncthreads();

    for (int step = 0; step < 3; step++) {
        float sval = 0.0f;
        if (tid < E) {
            const float* Ak = &sA[step * E * E];
            #pragma unroll 16
            for (int e = 0; e < E; e++) sval += scur[e] * Ak[e * E + tid];
            float s1 = sval, s2 = sval * sval;
            #pragma unroll
            for (int o = 16; o; o >>= 1) {
                s1 += __shfl_xor_sync(0xffffffffu, s1, o);
                s2 += __shfl_xor_sync(0xffffffffu, s2, o);
            }
            if ((tid & 31) == 0) { sred[(tid >> 5) * 2] = s1; sred[(tid >> 5) * 2 + 1] = s2; }
        }
        __syncthreads();
        if (tid < E) {
            float s1 = sred[0] + sred[2];
            float s2 = sred[1] + sred[3];
            float mu  = s1 * (1.0f / 64.0f);
            float var = s2 * (1.0f / 64.0f) - mu * mu;
            float inv = rsqrtf(var + 1e-6f);
            float iv  = ln_g[step * E + tid] * (sval - mu) * inv + ln_b[step * E + tid];
            scur[tid] = iv;
            ssum[tid] += iv;
        }
        __syncthreads();
    }

    if (tid < L) {
        float acc = 0.0f;
        #pragma unroll 8
        for (int f = 0; f < E; f++) acc += ssum[f] * Z[f * L + tid];
        out[(size_t)b * L + tid] = acc;
    }
}

// ---------------------------------------------------------------------------
extern "C" void kernel_launch(void* const* d_in, const int* in_sizes, int n_in,
                              void* d_out, int out_size)
{
    const float* x    = (const float*)d_in[0];
    const float* tpr  = (const float*)d_in[1];
    const float* eW1  = (const float*)d_in[2];
    const float* eb1  = (const float*)d_in[3];
    const float* eW2  = (const float*)d_in[4];
    const float* eb2  = (const float*)d_in[5];
    const float* rW1  = (const float*)d_in[6];
    const float* rb1  = (const float*)d_in[7];
    const float* rW2  = (const float*)d_in[8];
    const float* rb2  = (const float*)d_in[9];
    const float* ln_g = (const float*)d_in[10];
    const float* ln_b = (const float*)d_in[11];
    const float* Z    = (const float*)d_in[12];
    float* out = (float*)d_out;

    int B = in_sizes[0] / S;   // 1024

    dim3 g1(32, B / 32);
    k1_gemm_tanh<<<g1, 128>>>(x, eW1, eb1, rW1, rb1, B);

    dim3 g2(B / 32, 4, 2);
    size_t smem2 = (size_t)(32 * 36 + 32 * 68) * sizeof(float);
    k2_all<<<g2, 256, smem2>>>(eW2, eb2, rW2, rb2, B);

    k3a_contract<<<B * 4, 256>>>(tpr, B);

    size_t smem3 = (size_t)(3 * E * E + E + E + 8) * sizeof(float);
    cudaFuncSetAttribute(k3b_chain, cudaFuncAttributeMaxDynamicSharedMemorySize, (int)smem3);
    k3b_chain<<<B, 256, smem3>>>(ln_g, ln_b, Z, out, B);
}